// round 13
// baseline (speedup 1.0000x reference)
#include <cuda_runtime.h>
#include <cuda_bf16.h>
#include <math.h>
#include <stdint.h>

#define BSZ 128
#define NNODE 4096
#define F0 7680
#define F1 4032
#define F2 512
#define TT 512

// ---- GEMM tiling ----
#define TBM 128
#define TBN 128
#define TBK 64
#define SROWB 144                 // padded smem row stride in BYTES (72 bf16)
#define SMAT (128 * SROWB)        // 18432 B per matrix tile
#define SSTAGE (4 * SMAT)         // Ah, Al, Bh, Bl
#define SMEM_TOT (2 * SSTAGE)     // 147456 B

// ---- global scratch (no allocation allowed) ----
__device__ __align__(256) __nv_bfloat16 g_xhi [NNODE*(size_t)F0];
__device__ __align__(256) __nv_bfloat16 g_xlo [NNODE*(size_t)F0];
__device__ __align__(256) __nv_bfloat16 g_w1hi[8192*(size_t)F0];
__device__ __align__(256) __nv_bfloat16 g_w1lo[8192*(size_t)F0];
__device__ __align__(256) float         g_c1  [NNODE*(size_t)8192];
__device__ __align__(256) float         g_h1  [NNODE*(size_t)F1];
__device__ __align__(256) __nv_bfloat16 g_h1hi[NNODE*(size_t)F1];
__device__ __align__(256) __nv_bfloat16 g_h1lo[NNODE*(size_t)F1];
__device__ __align__(256) __nv_bfloat16 g_w2hi[1024*(size_t)F1];
__device__ __align__(256) __nv_bfloat16 g_w2lo[1024*(size_t)F1];
__device__ __align__(256) float         g_c2  [NNODE*(size_t)1024];
__device__ __align__(256) float         g_h2  [NNODE*(size_t)F2];
__device__ __align__(256) float         g_out0[TT*128*64];
__device__ __align__(256) float         g_flat[128*32768];
__device__ __align__(256) float         g_part[128*128*128];
__device__ __align__(256) float         g_m1  [128*128];

__device__ __forceinline__ float sigmf(float x){ return 1.f/(1.f+expf(-x)); }

__device__ __forceinline__ uint32_t smem_u32(const void* p){
    uint32_t a;
    asm("{ .reg .u64 t; cvta.to.shared.u64 t, %1; cvt.u32.u64 %0, t; }":"=r"(a):"l"(p));
    return a;
}

#define CP_ASYNC16(dst, src) asm volatile("cp.async.cg.shared.global [%0], [%1], 16;"::"r"(dst),"l"(src))
#define CP_COMMIT()          asm volatile("cp.async.commit_group;" ::: "memory")
#define CP_WAIT1()           asm volatile("cp.async.wait_group 1;" ::: "memory")

#define LDSM4(r0,r1,r2,r3,addr) \
    asm volatile("ldmatrix.sync.aligned.m8n8.x4.shared.b16 {%0,%1,%2,%3}, [%4];" \
        : "=r"(r0),"=r"(r1),"=r"(r2),"=r"(r3) : "r"(addr))

#define MMA16816(d,a,b0,b1) \
    asm volatile("mma.sync.aligned.m16n8k16.row.col.f32.bf16.bf16.f32 " \
        "{%0,%1,%2,%3},{%4,%5,%6,%7},{%8,%9},{%0,%1,%2,%3};" \
        : "+f"((d)[0]),"+f"((d)[1]),"+f"((d)[2]),"+f"((d)[3]) \
        : "r"((a)[0]),"r"((a)[1]),"r"((a)[2]),"r"((a)[3]),"r"(b0),"r"(b1))

// issue one stage's cp.async loads (4 tiles of 128x64 bf16)
__device__ __forceinline__ void g_issue(uint32_t sbase, int stage,
    const __nv_bfloat16* __restrict__ Ah, const __nv_bfloat16* __restrict__ Al,
    const __nv_bfloat16* __restrict__ Bh, const __nv_bfloat16* __restrict__ Bl,
    int bm, int bn, int K, int k0, int tid)
{
    const uint32_t st = sbase + stage * SSTAGE;
#pragma unroll
    for (int t = 0; t < 16; t++){
        const int m = t >> 2;                       // 0:Ah 1:Al 2:Bh 3:Bl (compile-time)
        int cm  = tid + (t & 3) * 256;              // 0..1023 within matrix
        int row = cm >> 3, col = cm & 7;            // col = 16B chunk
        const __nv_bfloat16* src =
            (m == 0) ? Ah : (m == 1) ? Al : (m == 2) ? Bh : Bl;
        int br = (m < 2) ? bm : bn;
        src += (size_t)(br + row) * K + k0 + col * 8;
        CP_ASYNC16(st + m * SMAT + row * SROWB + col * 16, src);
    }
}

// compute one stage (BK=64): 3-pass bf16 mma into fp32 acc
__device__ __forceinline__ void g_compute(uint32_t sbase, int stage,
    float acc[4][4][4], int warp_m, int warp_n, int lane)
{
    const uint32_t st = sbase + stage * SSTAGE;
    // A ldmatrix lane address: row = wm*64 + mf*16 + ((L>>3)&1)*8 + (L&7), col = kk + (L>>4)*8
    const int ra = warp_m * 64 + ((lane >> 3) & 1) * 8 + (lane & 7);
    const uint32_t a_off = (uint32_t)ra * SROWB + ((lane >> 4) * 8) * 2;
    // B ldmatrix lane address: row(n) = wn*32 + n2*16 + (L>>4)*8 + (L&7), col(k) = kk + ((L>>3)&1)*8
    const int rb = warp_n * 32 + (lane >> 4) * 8 + (lane & 7);
    const uint32_t b_off = (uint32_t)rb * SROWB + (((lane >> 3) & 1) * 8) * 2;

    const uint32_t aH = st + 0 * SMAT + a_off;
    const uint32_t aL = st + 1 * SMAT + a_off;
    const uint32_t bH = st + 2 * SMAT + b_off;
    const uint32_t bL = st + 3 * SMAT + b_off;

#pragma unroll
    for (int kk = 0; kk < 64; kk += 16){
        uint32_t ah[4][4], al[4][4], bh[2][4], bl[2][4];
#pragma unroll
        for (int mf = 0; mf < 4; mf++){
            LDSM4(ah[mf][0], ah[mf][1], ah[mf][2], ah[mf][3], aH + mf * 16 * SROWB + kk * 2);
            LDSM4(al[mf][0], al[mf][1], al[mf][2], al[mf][3], aL + mf * 16 * SROWB + kk * 2);
        }
#pragma unroll
        for (int n2 = 0; n2 < 2; n2++){
            LDSM4(bh[n2][0], bh[n2][1], bh[n2][2], bh[n2][3], bH + n2 * 16 * SROWB + kk * 2);
            LDSM4(bl[n2][0], bl[n2][1], bl[n2][2], bl[n2][3], bL + n2 * 16 * SROWB + kk * 2);
        }
#pragma unroll
        for (int mf = 0; mf < 4; mf++){
#pragma unroll
            for (int nf = 0; nf < 4; nf++){
                const int n2 = nf >> 1, h = (nf & 1) * 2;
                MMA16816(acc[mf][nf], ah[mf], bh[n2][h], bh[n2][h + 1]);   // hi*hi
                MMA16816(acc[mf][nf], ah[mf], bl[n2][h], bl[n2][h + 1]);   // hi*lo
                MMA16816(acc[mf][nf], al[mf], bh[n2][h], bh[n2][h + 1]);   // lo*hi
            }
        }
    }
}

// C[m,n] = sum_k (Ah+Al)[m,k]*(Bh+Bl)[n,k].  M,N multiples of 128, K of 64.
// grid.x = (M/128)*(N/128), supertile-swizzled (8x8 tiles); MT = M/128 (mult of 8).
__global__ __launch_bounds__(256, 1)
void gemm_bf16x3(const __nv_bfloat16* __restrict__ Ah, const __nv_bfloat16* __restrict__ Al,
                 const __nv_bfloat16* __restrict__ Bh, const __nv_bfloat16* __restrict__ Bl,
                 float* __restrict__ C, int K, int ldc, int MT)
{
    extern __shared__ char smem[];
    const uint32_t sbase = smem_u32(smem);
    const int tid = threadIdx.x, lane = tid & 31, wid = tid >> 5;
    const int warp_m = wid & 1, warp_n = wid >> 1;

    const int bid = blockIdx.x;
    const int stile = bid >> 6, r = bid & 63;
    const int nstm = MT >> 3;
    const int bm = ((stile % nstm) * 8 + (r & 7)) * TBM;
    const int bn = ((stile / nstm) * 8 + (r >> 3)) * TBN;

    float acc[4][4][4];
#pragma unroll
    for (int i = 0; i < 4; i++)
#pragma unroll
        for (int j = 0; j < 4; j++)
#pragma unroll
            for (int q = 0; q < 4; q++) acc[i][j][q] = 0.f;

    const int niter = K / TBK;
    g_issue(sbase, 0, Ah, Al, Bh, Bl, bm, bn, K, 0, tid);   CP_COMMIT();
    g_issue(sbase, 1, Ah, Al, Bh, Bl, bm, bn, K, TBK, tid); CP_COMMIT();

    for (int i = 0; i < niter; i++){
        CP_WAIT1();
        __syncthreads();
        g_compute(sbase, i & 1, acc, warp_m, warp_n, lane);
        __syncthreads();
        if (i + 2 < niter)
            g_issue(sbase, i & 1, Ah, Al, Bh, Bl, bm, bn, K, (i + 2) * TBK, tid);
        CP_COMMIT();
    }

    const int row0 = bm + warp_m * 64 + (lane >> 2);
    const int col0 = bn + warp_n * 32 + (lane & 3) * 2;
#pragma unroll
    for (int mf = 0; mf < 4; mf++){
#pragma unroll
        for (int nf = 0; nf < 4; nf++){
            float* p = C + (size_t)(row0 + mf * 16) * ldc + col0 + nf * 8;
            *(float2*)p = make_float2(acc[mf][nf][0], acc[mf][nf][1]);
            *(float2*)(p + (size_t)8 * ldc) = make_float2(acc[mf][nf][2], acc[mf][nf][3]);
        }
    }
}

// ---- fp32 -> bf16 hi/lo splits ----
__device__ __forceinline__ void sp1(float x, __nv_bfloat16& h, __nv_bfloat16& l){
    h = __float2bfloat16(x);
    l = __float2bfloat16(x - __bfloat162float(h));
}
__global__ void split_pair(const float* __restrict__ s, __nv_bfloat16* __restrict__ hi,
                           __nv_bfloat16* __restrict__ lo, int n4)
{
    for (int i = blockIdx.x * blockDim.x + threadIdx.x; i < n4; i += gridDim.x * blockDim.x){
        float4 v = ((const float4*)s)[i];
        __nv_bfloat16 h0,h1,h2,h3,l0,l1,l2,l3;
        sp1(v.x,h0,l0); sp1(v.y,h1,l1); sp1(v.z,h2,l2); sp1(v.w,h3,l3);
        ((__nv_bfloat162*)hi)[2*i]   = __nv_bfloat162(h0,h1);
        ((__nv_bfloat162*)hi)[2*i+1] = __nv_bfloat162(h2,h3);
        ((__nv_bfloat162*)lo)[2*i]   = __nv_bfloat162(l0,l1);
        ((__nv_bfloat162*)lo)[2*i+1] = __nv_bfloat162(l2,l3);
    }
}
// dst row r: r<rows_a -> wa[r]; gap<=r<gap+rows_b -> wb[r-gap]; else zeros
__global__ void split_cat(const float* __restrict__ wa, int rows_a,
                          const float* __restrict__ wb, int gap, int rows_b,
                          __nv_bfloat16* __restrict__ hi, __nv_bfloat16* __restrict__ lo, int Kc)
{
    const int r = blockIdx.x;
    const float* src = nullptr;
    if (r < rows_a) src = wa + (size_t)r * Kc;
    else if (r >= gap && r < gap + rows_b) src = wb + (size_t)(r - gap) * Kc;
    const size_t base = (size_t)r * Kc;
    for (int c = threadIdx.x * 4; c < Kc; c += blockDim.x * 4){
        float4 v = src ? *(const float4*)(src + c) : make_float4(0.f,0.f,0.f,0.f);
        __nv_bfloat16 h0,h1,h2,h3,l0,l1,l2,l3;
        sp1(v.x,h0,l0); sp1(v.y,h1,l1); sp1(v.z,h2,l2); sp1(v.w,h3,l3);
        ((__nv_bfloat162*)(hi+base+c))[0] = __nv_bfloat162(h0,h1);
        ((__nv_bfloat162*)(hi+base+c))[1] = __nv_bfloat162(h2,h3);
        ((__nv_bfloat162*)(lo+base+c))[0] = __nv_bfloat162(l0,l1);
        ((__nv_bfloat162*)(lo+base+c))[1] = __nv_bfloat162(l2,l3);
    }
}

// ---- fp32 SGEMM (MLP head only, tiny) ----
__global__ __launch_bounds__(256,2)
void sgemm_nt(const float* __restrict__ A, const float* __restrict__ B,
              float* __restrict__ C, int M, int N, int K, int kchunk)
{
    __shared__ float As[16][128], Bs[16][128];
    const int tid=threadIdx.x, bm=blockIdx.y*128, bn=blockIdx.x*128;
    const int kstart=blockIdx.z*kchunk, kend=min(kstart+kchunk,K);
    float* Cz = C + (size_t)blockIdx.z*(size_t)M*(size_t)N;
    const int lrow=tid>>2, lcol=(tid&3)<<2, tr=(tid>>4)<<3, tc=(tid&15)<<3;
    float acc[8][8];
#pragma unroll
    for(int i=0;i<8;i++)
#pragma unroll
        for(int j=0;j<8;j++) acc[i][j]=0.f;
    for(int k0=kstart;k0<kend;k0+=16){
#pragma unroll
        for(int rr=0;rr<2;rr++){
            int r=lrow+rr*64;
            int gm=bm+r;
            float4 av=make_float4(0,0,0,0);
            if(gm<M) av=*(const float4*)(A+(size_t)gm*K+k0+lcol);
            As[lcol][r]=av.x; As[lcol+1][r]=av.y; As[lcol+2][r]=av.z; As[lcol+3][r]=av.w;
            int gn=bn+r;
            float4 bv=make_float4(0,0,0,0);
            if(gn<N) bv=*(const float4*)(B+(size_t)gn*K+k0+lcol);
            Bs[lcol][r]=bv.x; Bs[lcol+1][r]=bv.y; Bs[lcol+2][r]=bv.z; Bs[lcol+3][r]=bv.w;
        }
        __syncthreads();
#pragma unroll
        for(int k=0;k<16;k++){
            float a[8],b[8];
#pragma unroll
            for(int i=0;i<8;i++) a[i]=As[k][tr+i];
#pragma unroll
            for(int j=0;j<8;j++) b[j]=Bs[k][tc+j];
#pragma unroll
            for(int i=0;i<8;i++)
#pragma unroll
                for(int j=0;j<8;j++) acc[i][j]+=a[i]*b[j];
        }
        __syncthreads();
    }
#pragma unroll
    for(int i=0;i<8;i++){
        int gm=bm+tr+i; if(gm>=M) continue;
#pragma unroll
        for(int j=0;j<8;j++){
            int gn=bn+tc+j;
            if(gn<N) Cz[(size_t)gm*N+gn]=acc[i][j];
        }
    }
}

// ---- aggregation + epilogue over concatenated GEMM output ----
// out[b*32+d, j] = relu( (1/32)*sum_s ew[b,s,d]*C[b*32+s, j] + C[b*32+d, voff+j] + bias[j] )
__global__ void agg_epi(const float* __restrict__ C, int ldc, int voff,
                        const float* __restrict__ ew, const float* __restrict__ bias,
                        float* __restrict__ out, int F)
{
    const int b=blockIdx.y, j0=blockIdx.x*64, tid=threadIdx.x;
    __shared__ float ews[32][33], us[32][65];
    for(int idx=tid; idx<1024; idx+=256) ews[idx>>5][idx&31]=ew[b*1024+idx];
    for(int idx=tid; idx<2048; idx+=256){
        int s=idx>>6, jj=idx&63;
        us[s][jj]=C[(size_t)(b*32+s)*ldc + j0+jj];
    }
    __syncthreads();
    for(int idx=tid; idx<2048; idx+=256){
        int d=idx>>6, jj=idx&63, j=j0+jj;
        float a0=0.f,a1=0.f;
#pragma unroll
        for(int s=0;s<32;s+=2){ a0+=ews[s][d]*us[s][jj]; a1+=ews[s+1][d]*us[s+1][jj]; }
        float val=(a0+a1)*(1.f/32.f) + C[(size_t)(b*32+d)*ldc + voff+j] + bias[j];
        out[(size_t)(b*32+d)*F + j]=fmaxf(val,0.f);
    }
}

// ---- LSTM ----
__global__ void lstm_layer0(const float* __restrict__ h2,
    const float* __restrict__ wf, const float* __restrict__ uf, const float* __restrict__ bif, const float* __restrict__ bhf,
    const float* __restrict__ wb, const float* __restrict__ ub, const float* __restrict__ bib, const float* __restrict__ bhb,
    float* __restrict__ out0)
{
    const int b=blockIdx.x, dir=blockIdx.y, r=threadIdx.x;
    const float* wih = dir?wb:wf; const float* whh = dir?ub:uf;
    const float bias = dir?(bib[r]+bhb[r]):(bif[r]+bhf[r]);
    float wi[32], wh[32];
#pragma unroll
    for(int i=0;i<32;i++) wi[i]=wih[r*32+i];
#pragma unroll
    for(int j=0;j<32;j++) wh[j]=whh[r*32+j];
    __shared__ float xs[32], hs[32], gb[128];
    float c=0.f;
    if(r<32) hs[r]=0.f;
    __syncthreads();
    for(int tt=0;tt<TT;tt++){
        int t = dir?(TT-1-tt):tt;
        if(r<32) xs[r]=h2[(size_t)(b*32+r)*F2 + t];
        __syncthreads();
        float g0=0,g1=0,g2=0,g3=0;
#pragma unroll
        for(int i=0;i<32;i+=4){ g0+=xs[i]*wi[i]; g1+=xs[i+1]*wi[i+1]; g2+=xs[i+2]*wi[i+2]; g3+=xs[i+3]*wi[i+3]; }
#pragma unroll
        for(int j=0;j<32;j+=4){ g0+=hs[j]*wh[j]; g1+=hs[j+1]*wh[j+1]; g2+=hs[j+2]*wh[j+2]; g3+=hs[j+3]*wh[j+3]; }
        gb[r]=bias+((g0+g1)+(g2+g3));
        __syncthreads();
        if(r<32){
            float ig=sigmf(gb[r]), fg=sigmf(gb[32+r]), gg=tanhf(gb[64+r]), og=sigmf(gb[96+r]);
            c=fg*c+ig*gg; float h=og*tanhf(c); hs[r]=h;
            out0[((size_t)t*128+b)*64 + dir*32 + r]=h;
        }
    }
}
__global__ void lstm_layer1(const float* __restrict__ in0,
    const float* __restrict__ wf, const float* __restrict__ uf, const float* __restrict__ bif, const float* __restrict__ bhf,
    const float* __restrict__ wb, const float* __restrict__ ub, const float* __restrict__ bib, const float* __restrict__ bhb,
    float* __restrict__ flat)
{
    const int b=blockIdx.x, dir=blockIdx.y, r=threadIdx.x;
    const float* wih = dir?wb:wf; const float* whh = dir?ub:uf;
    const float bias = dir?(bib[r]+bhb[r]):(bif[r]+bhf[r]);
    float wi[64], wh[32];
#pragma unroll
    for(int i=0;i<64;i++) wi[i]=wih[r*64+i];
#pragma unroll
    for(int j=0;j<32;j++) wh[j]=whh[r*32+j];
    __shared__ float xs[64], hs[32], gb[128];
    float c=0.f;
    if(r<32) hs[r]=0.f;
    __syncthreads();
    for(int tt=0;tt<TT;tt++){
        int t = dir?(TT-1-tt):tt;
        if(r<64) xs[r]=in0[((size_t)t*128+b)*64 + r];
        __syncthreads();
        float g0=0,g1=0,g2=0,g3=0;
#pragma unroll
        for(int i=0;i<64;i+=4){ g0+=xs[i]*wi[i]; g1+=xs[i+1]*wi[i+1]; g2+=xs[i+2]*wi[i+2]; g3+=xs[i+3]*wi[i+3]; }
#pragma unroll
        for(int j=0;j<32;j+=4){ g0+=hs[j]*wh[j]; g1+=hs[j+1]*wh[j+1]; g2+=hs[j+2]*wh[j+2]; g3+=hs[j+3]*wh[j+3]; }
        gb[r]=bias+((g0+g1)+(g2+g3));
        __syncthreads();
        if(r<32){
            float ig=sigmf(gb[r]), fg=sigmf(gb[32+r]), gg=tanhf(gb[64+r]), og=sigmf(gb[96+r]);
            c=fg*c+ig*gg; float h=og*tanhf(c); hs[r]=h;
            flat[(size_t)b*32768 + (size_t)t*64 + dir*32 + r]=h;
        }
    }
}

__global__ void mlp_reduce(const float* __restrict__ part, const float* __restrict__ bias,
                           float* __restrict__ m1)
{
    int idx=blockIdx.x*blockDim.x+threadIdx.x;
    float acc=0.f;
#pragma unroll 8
    for(int z=0;z<128;z++) acc+=part[(size_t)z*16384+idx];
    m1[idx]=fmaxf(acc+bias[idx&127],0.f);
}
__global__ void mlp_final(const float* __restrict__ m1, const float* __restrict__ wm2,
                          const float* __restrict__ bm2, float* __restrict__ out)
{
    int b=threadIdx.x;
    float a0=0.f,a1=0.f;
#pragma unroll
    for(int n=0;n<128;n+=2){ a0+=m1[b*128+n]*wm2[n]; a1+=m1[b*128+n+1]*wm2[n+1]; }
    out[b]=sigmf((a0+a1)+bm2[0]);
}

extern "C" void kernel_launch(void* const* d_in, const int* in_sizes, int n_in,
                              void* d_out, int out_size)
{
    (void)in_sizes;(void)n_in;(void)out_size;
    const float** in = (const float**)d_in;
    const float* x=in[0];   const float* ew=in[2];
    const float* w1r=in[3]; const float* b1=in[4]; const float* w1o=in[5];
    const float* w2r=in[6]; const float* b2=in[7]; const float* w2o=in[8];
    const float* wm1=in[9]; const float* bm1=in[10]; const float* wm2=in[11]; const float* bm2=in[12];

    __nv_bfloat16 *xhi,*xlo,*w1hi,*w1lo,*h1hi,*h1lo,*w2hi,*w2lo;
    float *c1,*h1,*c2,*h2,*out0,*flat,*part,*m1;
    cudaGetSymbolAddress((void**)&xhi,g_xhi);   cudaGetSymbolAddress((void**)&xlo,g_xlo);
    cudaGetSymbolAddress((void**)&w1hi,g_w1hi); cudaGetSymbolAddress((void**)&w1lo,g_w1lo);
    cudaGetSymbolAddress((void**)&c1,g_c1);     cudaGetSymbolAddress((void**)&h1,g_h1);
    cudaGetSymbolAddress((void**)&h1hi,g_h1hi); cudaGetSymbolAddress((void**)&h1lo,g_h1lo);
    cudaGetSymbolAddress((void**)&w2hi,g_w2hi); cudaGetSymbolAddress((void**)&w2lo,g_w2lo);
    cudaGetSymbolAddress((void**)&c2,g_c2);     cudaGetSymbolAddress((void**)&h2,g_h2);
    cudaGetSymbolAddress((void**)&out0,g_out0); cudaGetSymbolAddress((void**)&flat,g_flat);
    cudaGetSymbolAddress((void**)&part,g_part); cudaGetSymbolAddress((void**)&m1,g_m1);
    float* out=(float*)d_out;

    cudaFuncSetAttribute(gemm_bf16x3, cudaFuncAttributeMaxDynamicSharedMemorySize, SMEM_TOT);

    // ---- splits ----
    split_pair<<<2048,256>>>(x, xhi, xlo, NNODE*F0/4);
    split_cat<<<8192,256>>>(w1r, F1, w1o, 4096, F1, w1hi, w1lo, F0);

    // ---- layer 1: c1[4096 x 8192] = x @ [w1_rel | w1_root]^T  (bf16x3 HMMA) ----
    gemm_bf16x3<<<2048, 256, SMEM_TOT>>>(xhi, xlo, w1hi, w1lo, c1, F0, 8192, 32);
    agg_epi<<<dim3(63,BSZ),256>>>(c1, 8192, 4096, ew, b1, h1, F1);

    // ---- layer 2 ----
    split_pair<<<2048,256>>>(h1, h1hi, h1lo, NNODE*F1/4);
    split_cat<<<1024,256>>>(w2r, F2, w2o, F2, F2, w2hi, w2lo, F1);
    gemm_bf16x3<<<256, 256, SMEM_TOT>>>(h1hi, h1lo, w2hi, w2lo, c2, F1, 1024, 32);
    agg_epi<<<dim3(8,BSZ),256>>>(c2, 1024, 512, ew, b2, h2, F2);

    // ---- bidirectional LSTM, 2 layers ----
    lstm_layer0<<<dim3(BSZ,2),128>>>(h2, in[13],in[14],in[15],in[16], in[17],in[18],in[19],in[20], out0);
    lstm_layer1<<<dim3(BSZ,2),128>>>(out0, in[21],in[22],in[23],in[24], in[25],in[26],in[27],in[28], flat);

    // ---- MLP head ----
    sgemm_nt<<<dim3(1,1,128),256>>>(flat, wm1, part, 128, 128, 32768, 256);
    mlp_reduce<<<64,256>>>(part, bm1, m1);
    mlp_final<<<1,128>>>(m1, wm2, bm2, out);
}

// round 14
// speedup vs baseline: 1.0003x; 1.0003x over previous
#include <cuda_runtime.h>
#include <cuda_bf16.h>
#include <math.h>
#include <stdint.h>

#define BSZ 128
#define NNODE 4096
#define F0 7680
#define F1 4032
#define F2 512
#define TT 512

// ---- GEMM tiling ----
#define TBM 128
#define TBN 128
#define TBK 64
#define SROWB 144                 // padded smem row stride in BYTES (72 bf16)
#define SMAT (128 * SROWB)        // 18432 B per matrix tile
#define SSTAGE (4 * SMAT)         // Ah, Al, Bh, Bl
#define SMEM_TOT (2 * SSTAGE)     // 147456 B

// ---- global scratch (no allocation allowed) ----
__device__ __align__(256) __nv_bfloat16 g_xhi [NNODE*(size_t)F0];
__device__ __align__(256) __nv_bfloat16 g_xlo [NNODE*(size_t)F0];
__device__ __align__(256) __nv_bfloat16 g_w1hi[8192*(size_t)F0];
__device__ __align__(256) __nv_bfloat16 g_w1lo[8192*(size_t)F0];
__device__ __align__(256) float         g_c1  [NNODE*(size_t)8192];
__device__ __align__(256) float         g_h1  [NNODE*(size_t)F1];
__device__ __align__(256) __nv_bfloat16 g_h1hi[NNODE*(size_t)F1];
__device__ __align__(256) __nv_bfloat16 g_h1lo[NNODE*(size_t)F1];
__device__ __align__(256) __nv_bfloat16 g_w2hi[1024*(size_t)F1];
__device__ __align__(256) __nv_bfloat16 g_w2lo[1024*(size_t)F1];
__device__ __align__(256) float         g_c2  [NNODE*(size_t)1024];
__device__ __align__(256) float         g_h2  [NNODE*(size_t)F2];
__device__ __align__(256) float         g_out0[TT*128*64];
__device__ __align__(256) float         g_flat[128*32768];
__device__ __align__(256) float         g_part[128*128*128];
__device__ __align__(256) float         g_m1  [128*128];

__device__ __forceinline__ float sigmf(float x){ return 1.f/(1.f+expf(-x)); }

__device__ __forceinline__ uint32_t smem_u32(const void* p){
    uint32_t a;
    asm("{ .reg .u64 t; cvta.to.shared.u64 t, %1; cvt.u32.u64 %0, t; }":"=r"(a):"l"(p));
    return a;
}

#define CP_ASYNC16(dst, src) asm volatile("cp.async.cg.shared.global [%0], [%1], 16;"::"r"(dst),"l"(src))
#define CP_COMMIT()          asm volatile("cp.async.commit_group;" ::: "memory")
#define CP_WAIT1()           asm volatile("cp.async.wait_group 1;" ::: "memory")

#define LDSM4(r0,r1,r2,r3,addr) \
    asm volatile("ldmatrix.sync.aligned.m8n8.x4.shared.b16 {%0,%1,%2,%3}, [%4];" \
        : "=r"(r0),"=r"(r1),"=r"(r2),"=r"(r3) : "r"(addr))

#define MMA16816(d,a,b0,b1) \
    asm volatile("mma.sync.aligned.m16n8k16.row.col.f32.bf16.bf16.f32 " \
        "{%0,%1,%2,%3},{%4,%5,%6,%7},{%8,%9},{%0,%1,%2,%3};" \
        : "+f"((d)[0]),"+f"((d)[1]),"+f"((d)[2]),"+f"((d)[3]) \
        : "r"((a)[0]),"r"((a)[1]),"r"((a)[2]),"r"((a)[3]),"r"(b0),"r"(b1))

// issue one stage's cp.async loads (4 tiles of 128x64 bf16)
__device__ __forceinline__ void g_issue(uint32_t sbase, int stage,
    const __nv_bfloat16* __restrict__ Ah, const __nv_bfloat16* __restrict__ Al,
    const __nv_bfloat16* __restrict__ Bh, const __nv_bfloat16* __restrict__ Bl,
    int bm, int bn, int K, int k0, int tid)
{
    const uint32_t st = sbase + stage * SSTAGE;
#pragma unroll
    for (int t = 0; t < 16; t++){
        const int m = t >> 2;                       // 0:Ah 1:Al 2:Bh 3:Bl (compile-time)
        int cm  = tid + (t & 3) * 256;              // 0..1023 within matrix
        int row = cm >> 3, col = cm & 7;            // col = 16B chunk
        const __nv_bfloat16* src =
            (m == 0) ? Ah : (m == 1) ? Al : (m == 2) ? Bh : Bl;
        int br = (m < 2) ? bm : bn;
        src += (size_t)(br + row) * K + k0 + col * 8;
        CP_ASYNC16(st + m * SMAT + row * SROWB + col * 16, src);
    }
}

// compute one stage (BK=64): 3-pass bf16 mma into fp32 acc
__device__ __forceinline__ void g_compute(uint32_t sbase, int stage,
    float acc[4][4][4], int warp_m, int warp_n, int lane)
{
    const uint32_t st = sbase + stage * SSTAGE;
    // A ldmatrix lane address: row = wm*64 + mf*16 + ((L>>3)&1)*8 + (L&7), col = kk + (L>>4)*8
    const int ra = warp_m * 64 + ((lane >> 3) & 1) * 8 + (lane & 7);
    const uint32_t a_off = (uint32_t)ra * SROWB + ((lane >> 4) * 8) * 2;
    // B ldmatrix lane address: row(n) = wn*32 + n2*16 + (L>>4)*8 + (L&7), col(k) = kk + ((L>>3)&1)*8
    const int rb = warp_n * 32 + (lane >> 4) * 8 + (lane & 7);
    const uint32_t b_off = (uint32_t)rb * SROWB + (((lane >> 3) & 1) * 8) * 2;

    const uint32_t aH = st + 0 * SMAT + a_off;
    const uint32_t aL = st + 1 * SMAT + a_off;
    const uint32_t bH = st + 2 * SMAT + b_off;
    const uint32_t bL = st + 3 * SMAT + b_off;

#pragma unroll
    for (int kk = 0; kk < 64; kk += 16){
        uint32_t ah[4][4], al[4][4], bh[2][4], bl[2][4];
#pragma unroll
        for (int mf = 0; mf < 4; mf++){
            LDSM4(ah[mf][0], ah[mf][1], ah[mf][2], ah[mf][3], aH + mf * 16 * SROWB + kk * 2);
            LDSM4(al[mf][0], al[mf][1], al[mf][2], al[mf][3], aL + mf * 16 * SROWB + kk * 2);
        }
#pragma unroll
        for (int n2 = 0; n2 < 2; n2++){
            LDSM4(bh[n2][0], bh[n2][1], bh[n2][2], bh[n2][3], bH + n2 * 16 * SROWB + kk * 2);
            LDSM4(bl[n2][0], bl[n2][1], bl[n2][2], bl[n2][3], bL + n2 * 16 * SROWB + kk * 2);
        }
#pragma unroll
        for (int mf = 0; mf < 4; mf++){
#pragma unroll
            for (int nf = 0; nf < 4; nf++){
                const int n2 = nf >> 1, h = (nf & 1) * 2;
                MMA16816(acc[mf][nf], ah[mf], bh[n2][h], bh[n2][h + 1]);   // hi*hi
                MMA16816(acc[mf][nf], ah[mf], bl[n2][h], bl[n2][h + 1]);   // hi*lo
                MMA16816(acc[mf][nf], al[mf], bh[n2][h], bh[n2][h + 1]);   // lo*hi
            }
        }
    }
}

// C[m,n] = sum_k (Ah+Al)[m,k]*(Bh+Bl)[n,k].  M,N multiples of 128, K of 64.
// grid.x = (M/128)*(N/128), supertile-swizzled (8x8 tiles); MT = M/128 (mult of 8).
__global__ __launch_bounds__(256, 1)
void gemm_bf16x3(const __nv_bfloat16* __restrict__ Ah, const __nv_bfloat16* __restrict__ Al,
                 const __nv_bfloat16* __restrict__ Bh, const __nv_bfloat16* __restrict__ Bl,
                 float* __restrict__ C, int K, int ldc, int MT)
{
    extern __shared__ char smem[];
    const uint32_t sbase = smem_u32(smem);
    const int tid = threadIdx.x, lane = tid & 31, wid = tid >> 5;
    const int warp_m = wid & 1, warp_n = wid >> 1;

    const int bid = blockIdx.x;
    const int stile = bid >> 6, r = bid & 63;
    const int nstm = MT >> 3;
    const int bm = ((stile % nstm) * 8 + (r & 7)) * TBM;
    const int bn = ((stile / nstm) * 8 + (r >> 3)) * TBN;

    float acc[4][4][4];
#pragma unroll
    for (int i = 0; i < 4; i++)
#pragma unroll
        for (int j = 0; j < 4; j++)
#pragma unroll
            for (int q = 0; q < 4; q++) acc[i][j][q] = 0.f;

    const int niter = K / TBK;
    g_issue(sbase, 0, Ah, Al, Bh, Bl, bm, bn, K, 0, tid);   CP_COMMIT();
    g_issue(sbase, 1, Ah, Al, Bh, Bl, bm, bn, K, TBK, tid); CP_COMMIT();

    for (int i = 0; i < niter; i++){
        CP_WAIT1();
        __syncthreads();
        g_compute(sbase, i & 1, acc, warp_m, warp_n, lane);
        __syncthreads();
        if (i + 2 < niter)
            g_issue(sbase, i & 1, Ah, Al, Bh, Bl, bm, bn, K, (i + 2) * TBK, tid);
        CP_COMMIT();
    }

    const int row0 = bm + warp_m * 64 + (lane >> 2);
    const int col0 = bn + warp_n * 32 + (lane & 3) * 2;
#pragma unroll
    for (int mf = 0; mf < 4; mf++){
#pragma unroll
        for (int nf = 0; nf < 4; nf++){
            float* p = C + (size_t)(row0 + mf * 16) * ldc + col0 + nf * 8;
            *(float2*)p = make_float2(acc[mf][nf][0], acc[mf][nf][1]);
            *(float2*)(p + (size_t)8 * ldc) = make_float2(acc[mf][nf][2], acc[mf][nf][3]);
        }
    }
}

// ---- fp32 -> bf16 hi/lo splits ----
__device__ __forceinline__ void sp1(float x, __nv_bfloat16& h, __nv_bfloat16& l){
    h = __float2bfloat16(x);
    l = __float2bfloat16(x - __bfloat162float(h));
}
__global__ void split_pair(const float* __restrict__ s, __nv_bfloat16* __restrict__ hi,
                           __nv_bfloat16* __restrict__ lo, int n4)
{
    for (int i = blockIdx.x * blockDim.x + threadIdx.x; i < n4; i += gridDim.x * blockDim.x){
        float4 v = ((const float4*)s)[i];
        __nv_bfloat16 h0,h1,h2,h3,l0,l1,l2,l3;
        sp1(v.x,h0,l0); sp1(v.y,h1,l1); sp1(v.z,h2,l2); sp1(v.w,h3,l3);
        ((__nv_bfloat162*)hi)[2*i]   = __nv_bfloat162(h0,h1);
        ((__nv_bfloat162*)hi)[2*i+1] = __nv_bfloat162(h2,h3);
        ((__nv_bfloat162*)lo)[2*i]   = __nv_bfloat162(l0,l1);
        ((__nv_bfloat162*)lo)[2*i+1] = __nv_bfloat162(l2,l3);
    }
}
// dst row r: r<rows_a -> wa[r]; gap<=r<gap+rows_b -> wb[r-gap]; else zeros
__global__ void split_cat(const float* __restrict__ wa, int rows_a,
                          const float* __restrict__ wb, int gap, int rows_b,
                          __nv_bfloat16* __restrict__ hi, __nv_bfloat16* __restrict__ lo, int Kc)
{
    const int r = blockIdx.x;
    const float* src = nullptr;
    if (r < rows_a) src = wa + (size_t)r * Kc;
    else if (r >= gap && r < gap + rows_b) src = wb + (size_t)(r - gap) * Kc;
    const size_t base = (size_t)r * Kc;
    for (int c = threadIdx.x * 4; c < Kc; c += blockDim.x * 4){
        float4 v = src ? *(const float4*)(src + c) : make_float4(0.f,0.f,0.f,0.f);
        __nv_bfloat16 h0,h1,h2,h3,l0,l1,l2,l3;
        sp1(v.x,h0,l0); sp1(v.y,h1,l1); sp1(v.z,h2,l2); sp1(v.w,h3,l3);
        ((__nv_bfloat162*)(hi+base+c))[0] = __nv_bfloat162(h0,h1);
        ((__nv_bfloat162*)(hi+base+c))[1] = __nv_bfloat162(h2,h3);
        ((__nv_bfloat162*)(lo+base+c))[0] = __nv_bfloat162(l0,l1);
        ((__nv_bfloat162*)(lo+base+c))[1] = __nv_bfloat162(l2,l3);
    }
}

// ---- fp32 SGEMM (MLP head only, tiny) ----
__global__ __launch_bounds__(256,2)
void sgemm_nt(const float* __restrict__ A, const float* __restrict__ B,
              float* __restrict__ C, int M, int N, int K, int kchunk)
{
    __shared__ float As[16][128], Bs[16][128];
    const int tid=threadIdx.x, bm=blockIdx.y*128, bn=blockIdx.x*128;
    const int kstart=blockIdx.z*kchunk, kend=min(kstart+kchunk,K);
    float* Cz = C + (size_t)blockIdx.z*(size_t)M*(size_t)N;
    const int lrow=tid>>2, lcol=(tid&3)<<2, tr=(tid>>4)<<3, tc=(tid&15)<<3;
    float acc[8][8];
#pragma unroll
    for(int i=0;i<8;i++)
#pragma unroll
        for(int j=0;j<8;j++) acc[i][j]=0.f;
    for(int k0=kstart;k0<kend;k0+=16){
#pragma unroll
        for(int rr=0;rr<2;rr++){
            int r=lrow+rr*64;
            int gm=bm+r;
            float4 av=make_float4(0,0,0,0);
            if(gm<M) av=*(const float4*)(A+(size_t)gm*K+k0+lcol);
            As[lcol][r]=av.x; As[lcol+1][r]=av.y; As[lcol+2][r]=av.z; As[lcol+3][r]=av.w;
            int gn=bn+r;
            float4 bv=make_float4(0,0,0,0);
            if(gn<N) bv=*(const float4*)(B+(size_t)gn*K+k0+lcol);
            Bs[lcol][r]=bv.x; Bs[lcol+1][r]=bv.y; Bs[lcol+2][r]=bv.z; Bs[lcol+3][r]=bv.w;
        }
        __syncthreads();
#pragma unroll
        for(int k=0;k<16;k++){
            float a[8],b[8];
#pragma unroll
            for(int i=0;i<8;i++) a[i]=As[k][tr+i];
#pragma unroll
            for(int j=0;j<8;j++) b[j]=Bs[k][tc+j];
#pragma unroll
            for(int i=0;i<8;i++)
#pragma unroll
                for(int j=0;j<8;j++) acc[i][j]+=a[i]*b[j];
        }
        __syncthreads();
    }
#pragma unroll
    for(int i=0;i<8;i++){
        int gm=bm+tr+i; if(gm>=M) continue;
#pragma unroll
        for(int j=0;j<8;j++){
            int gn=bn+tc+j;
            if(gn<N) Cz[(size_t)gm*N+gn]=acc[i][j];
        }
    }
}

// ---- aggregation + epilogue over concatenated GEMM output ----
// out[b*32+d, j] = relu( (1/32)*sum_s ew[b,s,d]*C[b*32+s, j] + C[b*32+d, voff+j] + bias[j] )
__global__ void agg_epi(const float* __restrict__ C, int ldc, int voff,
                        const float* __restrict__ ew, const float* __restrict__ bias,
                        float* __restrict__ out, int F)
{
    const int b=blockIdx.y, j0=blockIdx.x*64, tid=threadIdx.x;
    __shared__ float ews[32][33], us[32][65];
    for(int idx=tid; idx<1024; idx+=256) ews[idx>>5][idx&31]=ew[b*1024+idx];
    for(int idx=tid; idx<2048; idx+=256){
        int s=idx>>6, jj=idx&63;
        us[s][jj]=C[(size_t)(b*32+s)*ldc + j0+jj];
    }
    __syncthreads();
    for(int idx=tid; idx<2048; idx+=256){
        int d=idx>>6, jj=idx&63, j=j0+jj;
        float a0=0.f,a1=0.f;
#pragma unroll
        for(int s=0;s<32;s+=2){ a0+=ews[s][d]*us[s][jj]; a1+=ews[s+1][d]*us[s+1][jj]; }
        float val=(a0+a1)*(1.f/32.f) + C[(size_t)(b*32+d)*ldc + voff+j] + bias[j];
        out[(size_t)(b*32+d)*F + j]=fmaxf(val,0.f);
    }
}

// ---- LSTM ----
__global__ void lstm_layer0(const float* __restrict__ h2,
    const float* __restrict__ wf, const float* __restrict__ uf, const float* __restrict__ bif, const float* __restrict__ bhf,
    const float* __restrict__ wb, const float* __restrict__ ub, const float* __restrict__ bib, const float* __restrict__ bhb,
    float* __restrict__ out0)
{
    const int b=blockIdx.x, dir=blockIdx.y, r=threadIdx.x;
    const float* wih = dir?wb:wf; const float* whh = dir?ub:uf;
    const float bias = dir?(bib[r]+bhb[r]):(bif[r]+bhf[r]);
    float wi[32], wh[32];
#pragma unroll
    for(int i=0;i<32;i++) wi[i]=wih[r*32+i];
#pragma unroll
    for(int j=0;j<32;j++) wh[j]=whh[r*32+j];
    __shared__ float xs[32], hs[32], gb[128];
    float c=0.f;
    if(r<32) hs[r]=0.f;
    __syncthreads();
    for(int tt=0;tt<TT;tt++){
        int t = dir?(TT-1-tt):tt;
        if(r<32) xs[r]=h2[(size_t)(b*32+r)*F2 + t];
        __syncthreads();
        float g0=0,g1=0,g2=0,g3=0;
#pragma unroll
        for(int i=0;i<32;i+=4){ g0+=xs[i]*wi[i]; g1+=xs[i+1]*wi[i+1]; g2+=xs[i+2]*wi[i+2]; g3+=xs[i+3]*wi[i+3]; }
#pragma unroll
        for(int j=0;j<32;j+=4){ g0+=hs[j]*wh[j]; g1+=hs[j+1]*wh[j+1]; g2+=hs[j+2]*wh[j+2]; g3+=hs[j+3]*wh[j+3]; }
        gb[r]=bias+((g0+g1)+(g2+g3));
        __syncthreads();
        if(r<32){
            float ig=sigmf(gb[r]), fg=sigmf(gb[32+r]), gg=tanhf(gb[64+r]), og=sigmf(gb[96+r]);
            c=fg*c+ig*gg; float h=og*tanhf(c); hs[r]=h;
            out0[((size_t)t*128+b)*64 + dir*32 + r]=h;
        }
    }
}
__global__ void lstm_layer1(const float* __restrict__ in0,
    const float* __restrict__ wf, const float* __restrict__ uf, const float* __restrict__ bif, const float* __restrict__ bhf,
    const float* __restrict__ wb, const float* __restrict__ ub, const float* __restrict__ bib, const float* __restrict__ bhb,
    float* __restrict__ flat)
{
    const int b=blockIdx.x, dir=blockIdx.y, r=threadIdx.x;
    const float* wih = dir?wb:wf; const float* whh = dir?ub:uf;
    const float bias = dir?(bib[r]+bhb[r]):(bif[r]+bhf[r]);
    float wi[64], wh[32];
#pragma unroll
    for(int i=0;i<64;i++) wi[i]=wih[r*64+i];
#pragma unroll
    for(int j=0;j<32;j++) wh[j]=whh[r*32+j];
    __shared__ float xs[64], hs[32], gb[128];
    float c=0.f;
    if(r<32) hs[r]=0.f;
    __syncthreads();
    for(int tt=0;tt<TT;tt++){
        int t = dir?(TT-1-tt):tt;
        if(r<64) xs[r]=in0[((size_t)t*128+b)*64 + r];
        __syncthreads();
        float g0=0,g1=0,g2=0,g3=0;
#pragma unroll
        for(int i=0;i<64;i+=4){ g0+=xs[i]*wi[i]; g1+=xs[i+1]*wi[i+1]; g2+=xs[i+2]*wi[i+2]; g3+=xs[i+3]*wi[i+3]; }
#pragma unroll
        for(int j=0;j<32;j+=4){ g0+=hs[j]*wh[j]; g1+=hs[j+1]*wh[j+1]; g2+=hs[j+2]*wh[j+2]; g3+=hs[j+3]*wh[j+3]; }
        gb[r]=bias+((g0+g1)+(g2+g3));
        __syncthreads();
        if(r<32){
            float ig=sigmf(gb[r]), fg=sigmf(gb[32+r]), gg=tanhf(gb[64+r]), og=sigmf(gb[96+r]);
            c=fg*c+ig*gg; float h=og*tanhf(c); hs[r]=h;
            flat[(size_t)b*32768 + (size_t)t*64 + dir*32 + r]=h;
        }
    }
}

__global__ void mlp_reduce(const float* __restrict__ part, const float* __restrict__ bias,
                           float* __restrict__ m1)
{
    int idx=blockIdx.x*blockDim.x+threadIdx.x;
    float acc=0.f;
#pragma unroll 8
    for(int z=0;z<128;z++) acc+=part[(size_t)z*16384+idx];
    m1[idx]=fmaxf(acc+bias[idx&127],0.f);
}
__global__ void mlp_final(const float* __restrict__ m1, const float* __restrict__ wm2,
                          const float* __restrict__ bm2, float* __restrict__ out)
{
    int b=threadIdx.x;
    float a0=0.f,a1=0.f;
#pragma unroll
    for(int n=0;n<128;n+=2){ a0+=m1[b*128+n]*wm2[n]; a1+=m1[b*128+n+1]*wm2[n+1]; }
    out[b]=sigmf((a0+a1)+bm2[0]);
}

extern "C" void kernel_launch(void* const* d_in, const int* in_sizes, int n_in,
                              void* d_out, int out_size)
{
    (void)in_sizes;(void)n_in;(void)out_size;
    const float** in = (const float**)d_in;
    const float* x=in[0];   const float* ew=in[2];
    const float* w1r=in[3]; const float* b1=in[4]; const float* w1o=in[5];
    const float* w2r=in[6]; const float* b2=in[7]; const float* w2o=in[8];
    const float* wm1=in[9]; const float* bm1=in[10]; const float* wm2=in[11]; const float* bm2=in[12];

    __nv_bfloat16 *xhi,*xlo,*w1hi,*w1lo,*h1hi,*h1lo,*w2hi,*w2lo;
    float *c1,*h1,*c2,*h2,*out0,*flat,*part,*m1;
    cudaGetSymbolAddress((void**)&xhi,g_xhi);   cudaGetSymbolAddress((void**)&xlo,g_xlo);
    cudaGetSymbolAddress((void**)&w1hi,g_w1hi); cudaGetSymbolAddress((void**)&w1lo,g_w1lo);
    cudaGetSymbolAddress((void**)&c1,g_c1);     cudaGetSymbolAddress((void**)&h1,g_h1);
    cudaGetSymbolAddress((void**)&h1hi,g_h1hi); cudaGetSymbolAddress((void**)&h1lo,g_h1lo);
    cudaGetSymbolAddress((void**)&w2hi,g_w2hi); cudaGetSymbolAddress((void**)&w2lo,g_w2lo);
    cudaGetSymbolAddress((void**)&c2,g_c2);     cudaGetSymbolAddress((void**)&h2,g_h2);
    cudaGetSymbolAddress((void**)&out0,g_out0); cudaGetSymbolAddress((void**)&flat,g_flat);
    cudaGetSymbolAddress((void**)&part,g_part); cudaGetSymbolAddress((void**)&m1,g_m1);
    float* out=(float*)d_out;

    cudaFuncSetAttribute(gemm_bf16x3, cudaFuncAttributeMaxDynamicSharedMemorySize, SMEM_TOT);

    // ---- splits ----
    split_pair<<<2048,256>>>(x, xhi, xlo, NNODE*F0/4);
    split_cat<<<8192,256>>>(w1r, F1, w1o, 4096, F1, w1hi, w1lo, F0);

    // ---- layer 1: c1[4096 x 8192] = x @ [w1_rel | w1_root]^T  (bf16x3 HMMA) ----
    gemm_bf16x3<<<2048, 256, SMEM_TOT>>>(xhi, xlo, w1hi, w1lo, c1, F0, 8192, 32);
    agg_epi<<<dim3(63,BSZ),256>>>(c1, 8192, 4096, ew, b1, h1, F1);

    // ---- layer 2 ----
    split_pair<<<2048,256>>>(h1, h1hi, h1lo, NNODE*F1/4);
    split_cat<<<1024,256>>>(w2r, F2, w2o, F2, F2, w2hi, w2lo, F1);
    gemm_bf16x3<<<256, 256, SMEM_TOT>>>(h1hi, h1lo, w2hi, w2lo, c2, F1, 1024, 32);
    agg_epi<<<dim3(8,BSZ),256>>>(c2, 1024, 512, ew, b2, h2, F2);

    // ---- bidirectional LSTM, 2 layers ----
    lstm_layer0<<<dim3(BSZ,2),128>>>(h2, in[13],in[14],in[15],in[16], in[17],in[18],in[19],in[20], out0);
    lstm_layer1<<<dim3(BSZ,2),128>>>(out0, in[21],in[22],in[23],in[24], in[25],in[26],in[27],in[28], flat);

    // ---- MLP head ----
    sgemm_nt<<<dim3(1,1,128),256>>>(flat, wm1, part, 128, 128, 32768, 256);
    mlp_reduce<<<64,256>>>(part, bm1, m1);
    mlp_final<<<1,128>>>(m1, wm2, bm2, out);
}